// round 2
// baseline (speedup 1.0000x reference)
#include <cuda_runtime.h>
#include <math.h>

// Mamba 6-branch fused pipeline, fp32 throughout.
// Shapes: B=2, L=2048, D_MODEL=256, D_INNER=512, D_STATE=16, DT_RANK=16, N_BRANCH=6
#define LSEQ 2048
#define DI   512
#define NB   6
#define NBATCH 2

// -------- scratch (device globals; no allocation allowed) --------
__device__ float  g_xz[NBATCH * 1024 * LSEQ];      // [b][e][l]          16 MB
__device__ float2 g_du[NB * NBATCH * DI * LSEQ];   // [i][b][d][t] x=delta y=u  ~100 MB
__device__ float  g_dtlow[NB * NBATCH * LSEQ * 16];// [ib][t][r]         1.5 MB
__device__ float2 g_bc[NB * NBATCH * LSEQ * 16];   // [ib][t][n] x=B y=C 3 MB
__device__ float  g_y[NB * NBATCH * DI * LSEQ];    // [i][b][d][t]       48 MB
__device__ float  g_total[NBATCH * DI * LSEQ];     // [b][d][l]          8 MB

// ---------------- K1: xz[b][e][l] = sum_d hs[b][l][d] * in_w[e][d] ----------------
__global__ void __launch_bounds__(256) k1_gemm_in(const float* __restrict__ hs,
                                                  const float* __restrict__ in_w)
{
    __shared__ float sa[16][68];  // [kk][e]
    __shared__ float sb[16][68];  // [kk][l]
    int b  = blockIdx.z;
    int e0 = blockIdx.y * 64;
    int l0 = blockIdx.x * 64;
    int tid = threadIdx.x;
    int tx = tid & 15, ty = tid >> 4;
    float acc[4][4];
#pragma unroll
    for (int ii = 0; ii < 4; ii++)
#pragma unroll
        for (int jj = 0; jj < 4; jj++) acc[ii][jj] = 0.f;

    int row = tid >> 2, kq = tid & 3;
    for (int k0 = 0; k0 < 256; k0 += 16) {
        float4 v = *(const float4*)&in_w[(e0 + row) * 256 + k0 + kq * 4];
        sa[kq * 4 + 0][row] = v.x; sa[kq * 4 + 1][row] = v.y;
        sa[kq * 4 + 2][row] = v.z; sa[kq * 4 + 3][row] = v.w;
        float4 w = *(const float4*)&hs[((size_t)b * 2048 + l0 + row) * 256 + k0 + kq * 4];
        sb[kq * 4 + 0][row] = w.x; sb[kq * 4 + 1][row] = w.y;
        sb[kq * 4 + 2][row] = w.z; sb[kq * 4 + 3][row] = w.w;
        __syncthreads();
#pragma unroll
        for (int kk = 0; kk < 16; kk++) {
            float4 ra = *(float4*)&sa[kk][ty * 4];
            float4 rb = *(float4*)&sb[kk][tx * 4];
            float av[4] = {ra.x, ra.y, ra.z, ra.w};
            float bv[4] = {rb.x, rb.y, rb.z, rb.w};
#pragma unroll
            for (int ii = 0; ii < 4; ii++)
#pragma unroll
                for (int jj = 0; jj < 4; jj++)
                    acc[ii][jj] = fmaf(av[ii], bv[jj], acc[ii][jj]);
        }
        __syncthreads();
    }
#pragma unroll
    for (int ii = 0; ii < 4; ii++) {
        float4 v = make_float4(acc[ii][0], acc[ii][1], acc[ii][2], acc[ii][3]);
        *(float4*)&g_xz[((size_t)b * 1024 + e0 + ty * 4 + ii) * LSEQ + l0 + tx * 4] = v;
    }
}

// permuted read index: scan position -> original l
__device__ __forceinline__ int perm_idx(int tau, int rev, int sft) {
    int base = rev ? (2047 - tau) : tau;
    return ((base & ((1 << sft) - 1)) << (11 - sft)) | (base >> sft);
}

// ---------------- K2: u = silu(causal dwconv over permuted x), write g_du.y ----------------
__global__ void __launch_bounds__(256) k2_conv(const float* __restrict__ conv_w,
                                               const float* __restrict__ conv_b)
{
    int gid = blockIdx.x * 256 + threadIdx.x;    // 6*2*512*256 threads
    int t8 = gid & 255;
    int d  = (gid >> 8) & 511;
    int b  = (gid >> 17) & 1;
    int i  = gid >> 18;
    int sft = (i < 2) ? 11 : ((i < 4) ? 6 : 4);
    int rev = i & 1;
    const float* xrow = g_xz + ((size_t)b * 1024 + d) * LSEQ;
    float w0 = conv_w[(i * 512 + d) * 4 + 0];
    float w1 = conv_w[(i * 512 + d) * 4 + 1];
    float w2 = conv_w[(i * 512 + d) * 4 + 2];
    float w3 = conv_w[(i * 512 + d) * 4 + 3];
    float cb = conv_b[i * 512 + d];
    int t0 = t8 * 8;
    float xv[11];
#pragma unroll
    for (int j = 0; j < 11; j++) {
        int tau = t0 - 3 + j;
        xv[j] = (tau < 0) ? 0.f : xrow[perm_idx(tau, rev, sft)];
    }
    float2* dup = g_du + ((size_t)(i * 2 + b) * 512 + d) * LSEQ;
#pragma unroll
    for (int j = 0; j < 8; j++) {
        float u = fmaf(w0, xv[j], fmaf(w1, xv[j + 1], fmaf(w2, xv[j + 2], fmaf(w3, xv[j + 3], cb))));
        float e = __expf(-fabsf(u));
        float s = ((u >= 0.f) ? u : u * e) / (1.f + e);
        dup[t0 + j].y = s;
    }
}

// ---------------- K3a: x_dbl[ib][r][t] = sum_d xproj_w[i][r][d]*u[ib][d][t] ----------------
__global__ void __launch_bounds__(192) k3a_xproj(const float* __restrict__ xproj_w)
{
    __shared__ float su[32][129];
    __shared__ float sw[48][33];
    int ib = blockIdx.y;
    int i  = ib >> 1;
    int t0 = blockIdx.x * 128;
    int tid = threadIdx.x;                 // 192
    int rq = tid >> 4, tc = tid & 15;
    int r0 = rq * 4;
    const float2* U = g_du + (size_t)ib * DI * LSEQ;
    const float*  W = xproj_w + i * 48 * 512;
    float acc[4][8];
#pragma unroll
    for (int q = 0; q < 4; q++)
#pragma unroll
        for (int j = 0; j < 8; j++) acc[q][j] = 0.f;

    for (int dk = 0; dk < 512; dk += 32) {
        for (int idx = tid; idx < 32 * 128; idx += 192) {
            int dd = idx >> 7, tt = idx & 127;
            su[dd][tt] = U[(size_t)(dk + dd) * LSEQ + t0 + tt].y;
        }
        for (int idx = tid; idx < 48 * 32; idx += 192) {
            int r = idx >> 5, dd = idx & 31;
            sw[r][dd] = W[r * 512 + dk + dd];
        }
        __syncthreads();
#pragma unroll 8
        for (int dd = 0; dd < 32; dd++) {
            float uv[8];
#pragma unroll
            for (int j = 0; j < 8; j++) uv[j] = su[dd][tc + j * 16];
#pragma unroll
            for (int q = 0; q < 4; q++) {
                float wv = sw[r0 + q][dd];
#pragma unroll
                for (int j = 0; j < 8; j++) acc[q][j] = fmaf(wv, uv[j], acc[q][j]);
            }
        }
        __syncthreads();
    }
    float* bcf = (float*)g_bc;
#pragma unroll
    for (int q = 0; q < 4; q++) {
        int r = r0 + q;
#pragma unroll
        for (int j = 0; j < 8; j++) {
            int t = t0 + tc + j * 16;
            float v = acc[q][j];
            if (r < 16) {
                g_dtlow[((size_t)ib * LSEQ + t) * 16 + r] = v;
            } else {
                int n    = (r < 32) ? (r - 16) : (r - 32);
                int comp = (r < 32) ? 0 : 1;
                bcf[(((size_t)ib * LSEQ + t) * 16 + n) * 2 + comp] = v;
            }
        }
    }
}

// ---------------- K3b: delta = softplus(dt_w @ dt_low + dt_b), write g_du.x ----------------
__global__ void __launch_bounds__(256) k3b_delta(const float* __restrict__ dt_w,
                                                 const float* __restrict__ dt_b)
{
    __shared__ float sdt[128][17];
    int ib = blockIdx.z, i = ib >> 1;
    int t0 = blockIdx.x * 128, d0 = blockIdx.y * 16;
    int tid = threadIdx.x;
    for (int idx = tid; idx < 128 * 4; idx += 256) {
        int tt = idx >> 2, quad = idx & 3;
        float4 v = *(const float4*)&g_dtlow[((size_t)ib * LSEQ + t0 + tt) * 16 + quad * 4];
        sdt[tt][quad * 4 + 0] = v.x; sdt[tt][quad * 4 + 1] = v.y;
        sdt[tt][quad * 4 + 2] = v.z; sdt[tt][quad * 4 + 3] = v.w;
    }
    __syncthreads();
    int dsub = tid >> 4, tc = tid & 15;
    int d = d0 + dsub;
    float wv[16];
#pragma unroll
    for (int r = 0; r < 16; r++) wv[r] = dt_w[(i * 512 + d) * 16 + r];
    float bias = dt_b[i * 512 + d];
    float2* dup = g_du + ((size_t)ib * 512 + d) * LSEQ;
#pragma unroll
    for (int j = 0; j < 8; j++) {
        int t = t0 + tc + j * 16;
        float a = bias;
#pragma unroll
        for (int r = 0; r < 16; r++) a = fmaf(wv[r], sdt[tc + j * 16][r], a);
        float sp = (a > 15.f) ? a : log1pf(__expf(a));
        dup[t].x = sp;
    }
}

// ---------------- K4: selective scan. warp = 2 channels, lane = state ----------------
__global__ void __launch_bounds__(256) k4_scan(const float* __restrict__ A_log,
                                               const float* __restrict__ D_skip)
{
    int W = blockIdx.x * 8 + (threadIdx.x >> 5);   // 3072 warps
    int lane = threadIdx.x & 31;
    int i = W >> 9;
    int b = (W >> 8) & 1;
    int dp = W & 255;
    int half = lane >> 4, n = lane & 15;
    int d = dp * 2 + half;
    int ib = i * 2 + b;
    float Aval = -__expf(A_log[(i * 512 + d) * 16 + n]);
    float Dsk  = D_skip[i * 512 + d];
    const float2* du  = g_du + ((size_t)ib * 512 + d) * LSEQ;
    const float2* bc  = g_bc + (size_t)ib * LSEQ * 16 + n;
    const float*  zrw = g_xz + ((size_t)b * 1024 + 512 + d) * LSEQ;
    float* yout = g_y + ((size_t)ib * 512 + d) * LSEQ;
    int sft = (i < 2) ? 11 : ((i < 4) ? 6 : 4);
    int msk = (1 << sft) - 1;
    int rev = i & 1;
    float h = 0.f;
#pragma unroll 4
    for (int t = 0; t < LSEQ; t++) {
        float2 dv  = du[t];
        float2 bcv = bc[(size_t)t * 16];
        float dA = __expf(dv.x * Aval);
        float dux = dv.x * dv.y;
        h = fmaf(dA, h, dux * bcv.x);
        float p = h * bcv.y;
        p += __shfl_xor_sync(0xffffffffu, p, 8);
        p += __shfl_xor_sync(0xffffffffu, p, 4);
        p += __shfl_xor_sync(0xffffffffu, p, 2);
        p += __shfl_xor_sync(0xffffffffu, p, 1);
        int base = rev ? (2047 - t) : t;
        int l = ((base & msk) << (11 - sft)) | (base >> sft);
        float z = zrw[l];
        float e = __expf(-fabsf(z));
        float sz = ((z >= 0.f) ? z : z * e) / (1.f + e);
        float val = (p + dv.y * Dsk) * sz;
        if (n == 0) yout[t] = val;
    }
}

// ---------------- K5: total[b][d][l] = sum over branches (inverse write maps) ----------------
__global__ void __launch_bounds__(256) k5_sum()
{
    int gid = blockIdx.x * 256 + threadIdx.x;    // 2*512*2048 = 2^21
    int l = gid & 2047;
    int d = (gid >> 11) & 511;
    int b = gid >> 20;
    int t64 = ((l & 31) << 6) | (l >> 5);
    int t16 = ((l & 127) << 4) | (l >> 7);
    size_t ch = (size_t)d * LSEQ;
    size_t per_ib = (size_t)512 * LSEQ;
    float s;
    s  = g_y[(0 * 2 + b) * per_ib + ch + l];
    s += g_y[(1 * 2 + b) * per_ib + ch + (2047 - l)];
    s += g_y[(2 * 2 + b) * per_ib + ch + t64];
    s += g_y[(3 * 2 + b) * per_ib + ch + t64];
    s += g_y[(4 * 2 + b) * per_ib + ch + t16];
    s += g_y[(5 * 2 + b) * per_ib + ch + t16];
    g_total[((size_t)b * 512 + d) * LSEQ + l] = s;
}

// ---------------- K6: out[b][l][o] = sum_d total[b][d][l] * out_w[o][d] ----------------
__global__ void __launch_bounds__(256) k6_gemm_out(const float* __restrict__ out_w,
                                                   float* __restrict__ out)
{
    __shared__ float sa[16][68];  // [kk][m]
    __shared__ float sb[16][68];  // [kk][o]
    int m0 = blockIdx.x * 64;     // m = b*2048 + l
    int o0 = blockIdx.y * 64;
    int b  = m0 >> 11;
    int l0 = m0 & 2047;
    int tid = threadIdx.x;
    int tx = tid & 15, ty = tid >> 4;
    float acc[4][4];
#pragma unroll
    for (int ii = 0; ii < 4; ii++)
#pragma unroll
        for (int jj = 0; jj < 4; jj++) acc[ii][jj] = 0.f;

    int rowa = tid >> 4, mq = tid & 15;
    int oloc = tid >> 2, kq = tid & 3;
    for (int k0 = 0; k0 < 512; k0 += 16) {
        float4 v = *(const float4*)&g_total[((size_t)b * 512 + k0 + rowa) * LSEQ + l0 + mq * 4];
        *(float4*)&sa[rowa][mq * 4] = v;
        float4 w = *(const float4*)&out_w[(o0 + oloc) * 512 + k0 + kq * 4];
        sb[kq * 4 + 0][oloc] = w.x; sb[kq * 4 + 1][oloc] = w.y;
        sb[kq * 4 + 2][oloc] = w.z; sb[kq * 4 + 3][oloc] = w.w;
        __syncthreads();
#pragma unroll
        for (int kk = 0; kk < 16; kk++) {
            float4 ra = *(float4*)&sa[kk][ty * 4];
            float4 rb = *(float4*)&sb[kk][tx * 4];
            float av[4] = {ra.x, ra.y, ra.z, ra.w};
            float bv[4] = {rb.x, rb.y, rb.z, rb.w};
#pragma unroll
            for (int ii = 0; ii < 4; ii++)
#pragma unroll
                for (int jj = 0; jj < 4; jj++)
                    acc[ii][jj] = fmaf(av[ii], bv[jj], acc[ii][jj]);
        }
        __syncthreads();
    }
#pragma unroll
    for (int ii = 0; ii < 4; ii++) {
        float4 v = make_float4(acc[ii][0], acc[ii][1], acc[ii][2], acc[ii][3]);
        *(float4*)&out[((size_t)m0 + ty * 4 + ii) * 256 + o0 + tx * 4] = v;
    }
}

extern "C" void kernel_launch(void* const* d_in, const int* in_sizes, int n_in,
                              void* d_out, int out_size)
{
    const float* hs      = (const float*)d_in[0];
    const float* in_w    = (const float*)d_in[1];
    const float* out_w   = (const float*)d_in[2];
    const float* conv_w  = (const float*)d_in[3];
    const float* conv_b  = (const float*)d_in[4];
    const float* xproj_w = (const float*)d_in[5];
    const float* dt_w    = (const float*)d_in[6];
    const float* dt_b    = (const float*)d_in[7];
    const float* A_log   = (const float*)d_in[8];
    const float* D_skip  = (const float*)d_in[9];
    float* out = (float*)d_out;

    dim3 g1(32, 16, 2);
    k1_gemm_in<<<g1, 256>>>(hs, in_w);
    k2_conv<<<6144, 256>>>(conv_w, conv_b);
    dim3 g3(16, 12);
    k3a_xproj<<<g3, 192>>>(xproj_w);
    dim3 g3b(16, 32, 12);
    k3b_delta<<<g3b, 256>>>(dt_w, dt_b);
    k4_scan<<<384, 256>>>(A_log, D_skip);
    k5_sum<<<8192, 256>>>();
    dim3 g6(64, 4);
    k6_gemm_out<<<g6, 256>>>(out_w, out);
}

// round 3
// speedup vs baseline: 4.4869x; 4.4869x over previous
#include <cuda_runtime.h>
#include <math.h>

// Mamba 6-branch fused pipeline, fp32, chunked parallel scan.
// B=2, L=2048, D_MODEL=256, D_INNER=512, N=16, DT_RANK=16, branches=6 (ib = i*2+b, 12 streams)
#define LSEQ 2048
#define DI   512
#define NIB  12
#define LC   128
#define NCH  16

// -------- scratch (device globals) --------
__device__ float g_xz[2 * LSEQ * 1024];        // [b][l][e]      16.8 MB
__device__ float g_u[NIB * LSEQ * DI];         // [ib][t][d]     50 MB
__device__ float g_delta[NIB * LSEQ * DI];     // [ib][t][d]     50 MB
__device__ float g_dtlow[NIB * LSEQ * 16];     // [ib][t][r]
__device__ float g_bcs[NIB * LSEQ * 32];       // [ib][t][s] s<16:B, s>=16:C
__device__ float g_P[NIB * NCH * DI * 16];     // chunk products
__device__ float g_q[NIB * NCH * DI * 16];     // chunk offsets
__device__ float g_hin[NIB * NCH * DI * 16];   // chunk entry states
__device__ float g_y[NIB * LSEQ * DI];         // [ib][t][d]     50 MB
__device__ float g_total[2 * LSEQ * DI];       // [b][l][d]

__device__ __forceinline__ float silu_f(float v) {
    float e = __expf(-fabsf(v));
    return ((v >= 0.f) ? v : v * e) / (1.f + e);
}

// ---------------- K1: xz[m][e] = sum_k hs[m][k]*in_w[e][k], m=b*2048+l ----------------
__global__ void __launch_bounds__(256) k1_gemm_in(const float* __restrict__ hs,
                                                  const float* __restrict__ in_w)
{
    __shared__ float sa[16][68];  // [kk][m]
    __shared__ float sb[16][68];  // [kk][e]
    int m0 = blockIdx.x * 64;
    int e0 = blockIdx.y * 64;
    int tid = threadIdx.x;
    int tx = tid & 15, ty = tid >> 4;
    float acc[4][4];
#pragma unroll
    for (int ii = 0; ii < 4; ii++)
#pragma unroll
        for (int jj = 0; jj < 4; jj++) acc[ii][jj] = 0.f;
    int row = tid >> 2, kq = tid & 3;
    for (int k0 = 0; k0 < 256; k0 += 16) {
        float4 va = *(const float4*)&hs[((size_t)m0 + row) * 256 + k0 + kq * 4];
        sa[kq * 4 + 0][row] = va.x; sa[kq * 4 + 1][row] = va.y;
        sa[kq * 4 + 2][row] = va.z; sa[kq * 4 + 3][row] = va.w;
        float4 vb = *(const float4*)&in_w[((size_t)e0 + row) * 256 + k0 + kq * 4];
        sb[kq * 4 + 0][row] = vb.x; sb[kq * 4 + 1][row] = vb.y;
        sb[kq * 4 + 2][row] = vb.z; sb[kq * 4 + 3][row] = vb.w;
        __syncthreads();
#pragma unroll
        for (int kk = 0; kk < 16; kk++) {
            float4 ra = *(float4*)&sa[kk][ty * 4];
            float4 rb = *(float4*)&sb[kk][tx * 4];
            float av[4] = {ra.x, ra.y, ra.z, ra.w};
            float bv[4] = {rb.x, rb.y, rb.z, rb.w};
#pragma unroll
            for (int ii = 0; ii < 4; ii++)
#pragma unroll
                for (int jj = 0; jj < 4; jj++)
                    acc[ii][jj] = fmaf(av[ii], bv[jj], acc[ii][jj]);
        }
        __syncthreads();
    }
#pragma unroll
    for (int ii = 0; ii < 4; ii++) {
        float4 v = make_float4(acc[ii][0], acc[ii][1], acc[ii][2], acc[ii][3]);
        *(float4*)&g_xz[((size_t)m0 + ty * 4 + ii) * 1024 + e0 + tx * 4] = v;
    }
}

// ---------------- K2: u[ib][t][d] = silu(causal dwconv of permuted x) ----------------
__global__ void __launch_bounds__(256) k2_conv(const float* __restrict__ conv_w,
                                               const float* __restrict__ conv_b)
{
    int ib = blockIdx.y;
    int t0 = blockIdx.x * 32;
    int i = ib >> 1, b = ib & 1;
    int sft = (i < 2) ? 11 : ((i < 4) ? 6 : 4);
    int rev = i & 1;
    int msk = (1 << sft) - 1;
    int d = threadIdx.x;  // handles d and d+256
    float w0a = conv_w[(i * 512 + d) * 4 + 0], w1a = conv_w[(i * 512 + d) * 4 + 1];
    float w2a = conv_w[(i * 512 + d) * 4 + 2], w3a = conv_w[(i * 512 + d) * 4 + 3];
    float w0b = conv_w[(i * 512 + d + 256) * 4 + 0], w1b = conv_w[(i * 512 + d + 256) * 4 + 1];
    float w2b = conv_w[(i * 512 + d + 256) * 4 + 2], w3b = conv_w[(i * 512 + d + 256) * 4 + 3];
    float cba = conv_b[i * 512 + d], cbb = conv_b[i * 512 + d + 256];
    const float* xb = g_xz + (size_t)b * LSEQ * 1024;
    for (int t = t0; t < t0 + 32; t++) {
        float a0 = cba, a1 = cbb;
#pragma unroll
        for (int k = 0; k < 4; k++) {
            int tau = t - 3 + k;
            if (tau >= 0) {
                int base = rev ? (2047 - tau) : tau;
                int l = ((base & msk) << (11 - sft)) | (base >> sft);
                float x0 = xb[(size_t)l * 1024 + d];
                float x1 = xb[(size_t)l * 1024 + d + 256];
                float wk0 = (k == 0) ? w0a : (k == 1) ? w1a : (k == 2) ? w2a : w3a;
                float wk1 = (k == 0) ? w0b : (k == 1) ? w1b : (k == 2) ? w2b : w3b;
                a0 = fmaf(wk0, x0, a0);
                a1 = fmaf(wk1, x1, a1);
            }
        }
        g_u[((size_t)ib * LSEQ + t) * 512 + d]       = silu_f(a0);
        g_u[((size_t)ib * LSEQ + t) * 512 + d + 256] = silu_f(a1);
    }
}

// ---------------- K3a: x_dbl[ib][t][r] = sum_d u[t][d]*xproj_w[i][r][d] ----------------
__global__ void __launch_bounds__(256) k3a_xproj(const float* __restrict__ xproj_w)
{
    __shared__ float su[64][65];  // [t][d]
    __shared__ float sw[48][65];  // [r][d]
    int ib = blockIdx.y, i = ib >> 1;
    int t0 = blockIdx.x * 64;
    int tid = threadIdx.x;
    int tx = tid & 15, ty = tid >> 4;  // tx: t-quad, ty: r-triple (48 = 16*3)
    float acc[4][3];
#pragma unroll
    for (int ii = 0; ii < 4; ii++)
#pragma unroll
        for (int j = 0; j < 3; j++) acc[ii][j] = 0.f;

    for (int dk = 0; dk < 512; dk += 64) {
#pragma unroll
        for (int p = 0; p < 4; p++) {
            int lin = tid + p * 256;
            int tt = lin >> 4, dq = lin & 15;
            float4 v = *(const float4*)&g_u[((size_t)ib * LSEQ + t0 + tt) * 512 + dk + dq * 4];
            su[tt][dq * 4 + 0] = v.x; su[tt][dq * 4 + 1] = v.y;
            su[tt][dq * 4 + 2] = v.z; su[tt][dq * 4 + 3] = v.w;
        }
#pragma unroll
        for (int p = 0; p < 3; p++) {
            int lin = tid + p * 256;
            int r = lin >> 4, dq = lin & 15;
            float4 v = *(const float4*)&xproj_w[((size_t)i * 48 + r) * 512 + dk + dq * 4];
            sw[r][dq * 4 + 0] = v.x; sw[r][dq * 4 + 1] = v.y;
            sw[r][dq * 4 + 2] = v.z; sw[r][dq * 4 + 3] = v.w;
        }
        __syncthreads();
#pragma unroll 8
        for (int dd = 0; dd < 64; dd++) {
            float u0 = su[tx * 4 + 0][dd];
            float u1 = su[tx * 4 + 1][dd];
            float u2 = su[tx * 4 + 2][dd];
            float u3 = su[tx * 4 + 3][dd];
#pragma unroll
            for (int j = 0; j < 3; j++) {
                float wv = sw[ty * 3 + j][dd];
                acc[0][j] = fmaf(u0, wv, acc[0][j]);
                acc[1][j] = fmaf(u1, wv, acc[1][j]);
                acc[2][j] = fmaf(u2, wv, acc[2][j]);
                acc[3][j] = fmaf(u3, wv, acc[3][j]);
            }
        }
        __syncthreads();
    }
#pragma unroll
    for (int ii = 0; ii < 4; ii++) {
        int t = t0 + tx * 4 + ii;
#pragma unroll
        for (int j = 0; j < 3; j++) {
            int r = ty * 3 + j;
            float v = acc[ii][j];
            if (r < 16) g_dtlow[((size_t)ib * LSEQ + t) * 16 + r] = v;
            else        g_bcs[((size_t)ib * LSEQ + t) * 32 + (r - 16)] = v;
        }
    }
}

// ---------------- K3b: delta[t][d] = softplus(dt_w[d]·dtlow[t] + dt_b[d]) ----------------
__global__ void __launch_bounds__(256) k3b_delta(const float* __restrict__ dt_w,
                                                 const float* __restrict__ dt_b)
{
    __shared__ float sdt[16][17];
    int ib = blockIdx.z, i = ib >> 1;
    int t0 = blockIdx.x * 16;
    int d = blockIdx.y * 256 + threadIdx.x;
    int tid = threadIdx.x;
    {
        int tt = tid >> 4, r = tid & 15;
        sdt[tt][r] = g_dtlow[((size_t)ib * LSEQ + t0 + tt) * 16 + r];
    }
    __syncthreads();
    float wv[16];
#pragma unroll
    for (int r = 0; r < 16; r++) wv[r] = dt_w[((size_t)i * 512 + d) * 16 + r];
    float bias = dt_b[i * 512 + d];
#pragma unroll
    for (int tt = 0; tt < 16; tt++) {
        float a = bias;
#pragma unroll
        for (int r = 0; r < 16; r++) a = fmaf(wv[r], sdt[tt][r], a);
        float sp = (a > 15.f) ? a : log1pf(__expf(a));
        g_delta[((size_t)ib * LSEQ + t0 + tt) * 512 + d] = sp;
    }
}

// ---------------- K4a: per-chunk scan from h=0; emit P, q ----------------
__global__ void __launch_bounds__(256) k4a_chunk(const float* __restrict__ A_log)
{
    __shared__ float sbc[32][32];
    int bi = blockIdx.x;          // 384 = 12 ib * 16 c * 2 half
    int half = bi & 1;
    int c = (bi >> 1) & 15;
    int ib = bi >> 5;
    int i = ib >> 1;
    int d = half * 256 + threadIdx.x;
    int tid = threadIdx.x;
    float Av[16];
#pragma unroll
    for (int n = 0; n < 16; n++) Av[n] = -__expf(A_log[((size_t)i * 512 + d) * 16 + n]);
    float h[16];
#pragma unroll
    for (int n = 0; n < 16; n++) h[n] = 0.f;
    float S = 0.f;

    for (int sub = 0; sub < 4; sub++) {
        int tb = c * LC + sub * 32;
        __syncthreads();
        {
            int tt = tid >> 3, s4 = tid & 7;
            float4 v = *(const float4*)&g_bcs[((size_t)ib * LSEQ + tb + tt) * 32 + s4 * 4];
            *(float4*)&sbc[tt][s4 * 4] = v;
        }
        __syncthreads();
#pragma unroll 2
        for (int tt = 0; tt < 32; tt++) {
            int t = tb + tt;
            float delta = g_delta[((size_t)ib * LSEQ + t) * 512 + d];
            float u     = g_u[((size_t)ib * LSEQ + t) * 512 + d];
            float dub = delta * u;
            S += delta;
#pragma unroll
            for (int n0 = 0; n0 < 16; n0 += 4) {
                float4 bn = *(float4*)&sbc[tt][n0];
                h[n0 + 0] = fmaf(__expf(delta * Av[n0 + 0]), h[n0 + 0], dub * bn.x);
                h[n0 + 1] = fmaf(__expf(delta * Av[n0 + 1]), h[n0 + 1], dub * bn.y);
                h[n0 + 2] = fmaf(__expf(delta * Av[n0 + 2]), h[n0 + 2], dub * bn.z);
                h[n0 + 3] = fmaf(__expf(delta * Av[n0 + 3]), h[n0 + 3], dub * bn.w);
            }
        }
    }
    size_t base = (((size_t)ib * 16 + c) * 512 + d) * 16;
#pragma unroll
    for (int n = 0; n < 16; n++) {
        g_P[base + n] = __expf(Av[n] * S);
        g_q[base + n] = h[n];
    }
}

// ---------------- K4b: inter-chunk scan (16 steps) ----------------
__global__ void __launch_bounds__(256) k4b_carry()
{
    int gid = blockIdx.x * 256 + threadIdx.x;  // 98304 = 12*512*16
    float h = 0.f;
    size_t base0 = (size_t)gid % (512 * 16);
    int ib = gid / (512 * 16);
    size_t stride = (size_t)512 * 16;
    size_t b0 = (size_t)ib * 16 * stride + base0;
    for (int c = 0; c < 16; c++) {
        size_t idx = b0 + c * stride;
        g_hin[idx] = h;
        h = fmaf(g_P[idx], h, g_q[idx]);
    }
}

// ---------------- K4c: replay with correct h_in; emit gated y ----------------
__global__ void __launch_bounds__(256) k4c_scan(const float* __restrict__ A_log,
                                                const float* __restrict__ D_skip)
{
    __shared__ float sbc[32][32];
    int bi = blockIdx.x;
    int half = bi & 1;
    int c = (bi >> 1) & 15;
    int ib = bi >> 5;
    int i = ib >> 1, b = ib & 1;
    int d = half * 256 + threadIdx.x;
    int tid = threadIdx.x;
    int sft = (i < 2) ? 11 : ((i < 4) ? 6 : 4);
    int rev = i & 1;
    int msk = (1 << sft) - 1;
    float Av[16];
#pragma unroll
    for (int n = 0; n < 16; n++) Av[n] = -__expf(A_log[((size_t)i * 512 + d) * 16 + n]);
    float Dsk = D_skip[i * 512 + d];
    float h[16];
    {
        size_t base = (((size_t)ib * 16 + c) * 512 + d) * 16;
#pragma unroll
        for (int n = 0; n < 16; n++) h[n] = g_hin[base + n];
    }
    const float* zb = g_xz + (size_t)b * LSEQ * 1024 + 512;

    for (int sub = 0; sub < 4; sub++) {
        int tb = c * LC + sub * 32;
        __syncthreads();
        {
            int tt = tid >> 3, s4 = tid & 7;
            float4 v = *(const float4*)&g_bcs[((size_t)ib * LSEQ + tb + tt) * 32 + s4 * 4];
            *(float4*)&sbc[tt][s4 * 4] = v;
        }
        __syncthreads();
#pragma unroll 2
        for (int tt = 0; tt < 32; tt++) {
            int t = tb + tt;
            float delta = g_delta[((size_t)ib * LSEQ + t) * 512 + d];
            float u     = g_u[((size_t)ib * LSEQ + t) * 512 + d];
            float dub = delta * u;
            float y = 0.f;
#pragma unroll
            for (int n0 = 0; n0 < 16; n0 += 4) {
                float4 bn = *(float4*)&sbc[tt][n0];
                float4 cn = *(float4*)&sbc[tt][16 + n0];
                h[n0 + 0] = fmaf(__expf(delta * Av[n0 + 0]), h[n0 + 0], dub * bn.x);
                y = fmaf(h[n0 + 0], cn.x, y);
                h[n0 + 1] = fmaf(__expf(delta * Av[n0 + 1]), h[n0 + 1], dub * bn.y);
                y = fmaf(h[n0 + 1], cn.y, y);
                h[n0 + 2] = fmaf(__expf(delta * Av[n0 + 2]), h[n0 + 2], dub * bn.z);
                y = fmaf(h[n0 + 2], cn.z, y);
                h[n0 + 3] = fmaf(__expf(delta * Av[n0 + 3]), h[n0 + 3], dub * bn.w);
                y = fmaf(h[n0 + 3], cn.w, y);
            }
            int base = rev ? (2047 - t) : t;
            int l = ((base & msk) << (11 - sft)) | (base >> sft);
            float z = zb[(size_t)l * 1024 + d];
            float out = (y + u * Dsk) * silu_f(z);
            g_y[((size_t)ib * LSEQ + t) * 512 + d] = out;
        }
    }
}

// ---------------- K5: total[b][l][d] = sum over branches ----------------
__global__ void __launch_bounds__(256) k5_sum()
{
    int gid = blockIdx.x * 256 + threadIdx.x;  // 2*2048*512
    int d = gid & 511;
    int l = (gid >> 9) & 2047;
    int b = gid >> 20;
    int t64 = ((l & 31) << 6) | (l >> 5);
    int t16 = ((l & 127) << 4) | (l >> 7);
    size_t per_ib = (size_t)LSEQ * 512;
    float s;
    s  = g_y[(0 + b) * per_ib + (size_t)l * 512 + d];
    s += g_y[(2 + b) * per_ib + (size_t)(2047 - l) * 512 + d];
    s += g_y[(4 + b) * per_ib + (size_t)t64 * 512 + d];
    s += g_y[(6 + b) * per_ib + (size_t)t64 * 512 + d];
    s += g_y[(8 + b) * per_ib + (size_t)t16 * 512 + d];
    s += g_y[(10 + b) * per_ib + (size_t)t16 * 512 + d];
    g_total[((size_t)b * LSEQ + l) * 512 + d] = s;
}

// ---------------- K6: out[m][o] = sum_k total[m][k]*out_w[o][k] ----------------
__global__ void __launch_bounds__(256) k6_gemm_out(const float* __restrict__ out_w,
                                                   float* __restrict__ out)
{
    __shared__ float sa[16][68];  // [kk][m]
    __shared__ float sb[16][68];  // [kk][o]
    int m0 = blockIdx.x * 64;
    int o0 = blockIdx.y * 64;
    int tid = threadIdx.x;
    int tx = tid & 15, ty = tid >> 4;
    float acc[4][4];
#pragma unroll
    for (int ii = 0; ii < 4; ii++)
#pragma unroll
        for (int jj = 0; jj < 4; jj++) acc[ii][jj] = 0.f;
    int row = tid >> 2, kq = tid & 3;
    for (int k0 = 0; k0 < 512; k0 += 16) {
        float4 va = *(const float4*)&g_total[((size_t)m0 + row) * 512 + k0 + kq * 4];
        sa[kq * 4 + 0][row] = va.x; sa[kq * 4 + 1][row] = va.y;
        sa[kq * 4 + 2][row] = va.z; sa[kq * 4 + 3][row] = va.w;
        float4 vb = *(const float4*)&out_w[((size_t)o0 + row) * 512 + k0 + kq * 4];
        sb[kq * 4 + 0][row] = vb.x; sb[kq * 4 + 1][row] = vb.y;
        sb[kq * 4 + 2][row] = vb.z; sb[kq * 4 + 3][row] = vb.w;
        __syncthreads();
#pragma unroll
        for (int kk = 0; kk < 16; kk++) {
            float4 ra = *(float4*)&sa[kk][ty * 4];
            float4 rb = *(float4*)&sb[kk][tx * 4];
            float av[4] = {ra.x, ra.y, ra.z, ra.w};
            float bv[4] = {rb.x, rb.y, rb.z, rb.w};
#pragma unroll
            for (int ii = 0; ii < 4; ii++)
#pragma unroll
                for (int jj = 0; jj < 4; jj++)
                    acc[ii][jj] = fmaf(av[ii], bv[jj], acc[ii][jj]);
        }
        __syncthreads();
    }
#pragma unroll
    for (int ii = 0; ii < 4; ii++) {
        float4 v = make_float4(acc[ii][0], acc[ii][1], acc[ii][2], acc[ii][3]);
        *(float4*)&out[((size_t)m0 + ty * 4 + ii) * 256 + o0 + tx * 4] = v;
    }
}

extern "C" void kernel_launch(void* const* d_in, const int* in_sizes, int n_in,
                              void* d_out, int out_size)
{
    const float* hs      = (const float*)d_in[0];
    const float* in_w    = (const float*)d_in[1];
    const float* out_w   = (const float*)d_in[2];
    const float* conv_w  = (const float*)d_in[3];
    const float* conv_b  = (const float*)d_in[4];
    const float* xproj_w = (const float*)d_in[5];
    const float* dt_w    = (const float*)d_in[6];
    const float* dt_b    = (const float*)d_in[7];
    const float* A_log   = (const float*)d_in[8];
    const float* D_skip  = (const float*)d_in[9];
    float* out = (float*)d_out;

    k1_gemm_in<<<dim3(64, 16), 256>>>(hs, in_w);
    k2_conv<<<dim3(64, 12), 256>>>(conv_w, conv_b);
    k3a_xproj<<<dim3(32, 12), 256>>>(xproj_w);
    k3b_delta<<<dim3(128, 2, 12), 256>>>(dt_w, dt_b);
    k4a_chunk<<<384, 256>>>(A_log);
    k4b_carry<<<384, 256>>>();
    k4c_scan<<<384, 256>>>(A_log, D_skip);
    k5_sum<<<8192, 256>>>();
    k6_gemm_out<<<dim3(64, 4), 256>>>(out_w, out);
}

// round 4
// speedup vs baseline: 4.5400x; 1.0118x over previous
#include <cuda_runtime.h>
#include <math.h>

// Mamba 6-branch fused pipeline, fp32, chunked parallel scan, fused conv/delta.
// B=2, L=2048, D_MODEL=256, D_INNER=512, N=16, DT_RANK=16, 12 (branch,batch) streams
#define LSEQ 2048
#define DI   512
#define NIB  12
#define LC   128
#define NCH  16

typedef unsigned long long ull;

// -------- scratch (device globals) --------
__device__ float g_xz[2 * LSEQ * 1024];        // [b][l][e]
__device__ float g_dtlow[NIB * LSEQ * 16];     // [ib][t][r]
__device__ float g_bcs[NIB * LSEQ * 32];       // [ib][t][s] s<16:B, s>=16:C
__device__ float g_P[NIB * NCH * DI * 16];
__device__ float g_q[NIB * NCH * DI * 16];
__device__ float g_hin[NIB * NCH * DI * 16];
__device__ float g_y[NIB * LSEQ * DI];         // [ib][t][d]
__device__ float g_total[2 * LSEQ * DI];       // [b][l][d]

__device__ __forceinline__ float silu_f(float v) {
    float e = __expf(-fabsf(v));
    return ((v >= 0.f) ? v : v * e) / (1.f + e);
}
__device__ __forceinline__ int perm_idx(int tau, int rev, int sft, int msk) {
    int base = rev ? (2047 - tau) : tau;
    return ((base & msk) << (11 - sft)) | (base >> sft);
}
__device__ __forceinline__ ull pack2(float lo, float hi) {
    ull r; asm("mov.b64 %0, {%1,%2};" : "=l"(r) : "f"(lo), "f"(hi)); return r;
}
__device__ __forceinline__ void ffma2(ull& d, ull a, ull b) {
    asm("fma.rn.f32x2 %0, %1, %2, %0;" : "+l"(d) : "l"(a), "l"(b));
}
__device__ __forceinline__ float2 unpack2(ull v) {
    float2 f; asm("mov.b64 {%0,%1}, %2;" : "=f"(f.x), "=f"(f.y) : "l"(v)); return f;
}

// ---------------- K1: xz[m][e] = sum_k hs[m][k]*in_w[e][k] (M=4096,N=1024,K=256) ----------------
__global__ void __launch_bounds__(256) k1_gemm_in(const float* __restrict__ hs,
                                                  const float* __restrict__ in_w)
{
    __shared__ __align__(16) float sa[16][132];
    __shared__ __align__(16) float sb[16][132];
    int m0 = blockIdx.x * 128, n0 = blockIdx.y * 128;
    int tid = threadIdx.x;
    int tx = tid & 15, ty = tid >> 4;
    ull acc[8][4];
#pragma unroll
    for (int ii = 0; ii < 8; ii++)
#pragma unroll
        for (int jj = 0; jj < 4; jj++) acc[ii][jj] = 0ull;
    int rowa = tid >> 1, kh = (tid & 1) * 8;
    for (int k0 = 0; k0 < 256; k0 += 16) {
#pragma unroll
        for (int q = 0; q < 2; q++) {
            float4 v = *(const float4*)&hs[(size_t)(m0 + rowa) * 256 + k0 + kh + q * 4];
            sa[kh + q * 4 + 0][rowa] = v.x; sa[kh + q * 4 + 1][rowa] = v.y;
            sa[kh + q * 4 + 2][rowa] = v.z; sa[kh + q * 4 + 3][rowa] = v.w;
            float4 w = *(const float4*)&in_w[(size_t)(n0 + rowa) * 256 + k0 + kh + q * 4];
            sb[kh + q * 4 + 0][rowa] = w.x; sb[kh + q * 4 + 1][rowa] = w.y;
            sb[kh + q * 4 + 2][rowa] = w.z; sb[kh + q * 4 + 3][rowa] = w.w;
        }
        __syncthreads();
#pragma unroll
        for (int kk = 0; kk < 16; kk++) {
            float4 a0 = *(float4*)&sa[kk][ty * 8];
            float4 a1 = *(float4*)&sa[kk][ty * 8 + 4];
            float4 b0 = *(float4*)&sb[kk][tx * 8];
            float4 b1 = *(float4*)&sb[kk][tx * 8 + 4];
            ull bp[4] = {pack2(b0.x, b0.y), pack2(b0.z, b0.w),
                         pack2(b1.x, b1.y), pack2(b1.z, b1.w)};
            float av[8] = {a0.x, a0.y, a0.z, a0.w, a1.x, a1.y, a1.z, a1.w};
#pragma unroll
            for (int ii = 0; ii < 8; ii++) {
                ull ap = pack2(av[ii], av[ii]);
#pragma unroll
                for (int jj = 0; jj < 4; jj++) ffma2(acc[ii][jj], ap, bp[jj]);
            }
        }
        __syncthreads();
    }
#pragma unroll
    for (int ii = 0; ii < 8; ii++) {
        float2 c0 = unpack2(acc[ii][0]), c1 = unpack2(acc[ii][1]);
        float2 c2 = unpack2(acc[ii][2]), c3 = unpack2(acc[ii][3]);
        float4 v0 = make_float4(c0.x, c0.y, c1.x, c1.y);
        float4 v1 = make_float4(c2.x, c2.y, c3.x, c3.y);
        size_t base = (size_t)(m0 + ty * 8 + ii) * 1024 + n0 + tx * 8;
        *(float4*)&g_xz[base]     = v0;
        *(float4*)&g_xz[base + 4] = v1;
    }
}

// ---------------- K3a: fused conv+silu u, then x_dbl[ib][t][r] = sum_d u[t][d]*xproj_w[i][r][d] ----------------
__global__ void __launch_bounds__(256) k3a_xproj(const float* __restrict__ xproj_w,
                                                 const float* __restrict__ conv_w,
                                                 const float* __restrict__ conv_b)
{
    __shared__ float su[64][65];
    __shared__ float sw[48][65];
    int ib = blockIdx.y, i = ib >> 1, b = ib & 1;
    int t0 = blockIdx.x * 64;
    int tid = threadIdx.x;
    int tx = tid & 15, ty = tid >> 4;
    int sft = (i < 2) ? 11 : ((i < 4) ? 6 : 4);
    int rev = i & 1;
    int msk = (1 << sft) - 1;
    const float* xb = g_xz + (size_t)b * LSEQ * 1024;
    float acc[4][3];
#pragma unroll
    for (int ii = 0; ii < 4; ii++)
#pragma unroll
        for (int j = 0; j < 3; j++) acc[ii][j] = 0.f;

    for (int dk = 0; dk < 512; dk += 64) {
#pragma unroll
        for (int p = 0; p < 4; p++) {
            int lin = tid + p * 256;
            int tt = lin >> 4, dq = (lin & 15) * 4;
            int dcol = dk + dq;
            float4 wv0 = *(const float4*)&conv_w[((size_t)i * 512 + dcol + 0) * 4];
            float4 wv1 = *(const float4*)&conv_w[((size_t)i * 512 + dcol + 1) * 4];
            float4 wv2 = *(const float4*)&conv_w[((size_t)i * 512 + dcol + 2) * 4];
            float4 wv3 = *(const float4*)&conv_w[((size_t)i * 512 + dcol + 3) * 4];
            float4 a = *(const float4*)&conv_b[i * 512 + dcol];
#pragma unroll
            for (int k = 0; k < 4; k++) {
                int tau = t0 + tt - 3 + k;
                if (tau >= 0) {
                    int l = perm_idx(tau, rev, sft, msk);
                    float4 xv = *(const float4*)&xb[(size_t)l * 1024 + dcol];
                    float w0 = (k == 0) ? wv0.x : (k == 1) ? wv0.y : (k == 2) ? wv0.z : wv0.w;
                    float w1 = (k == 0) ? wv1.x : (k == 1) ? wv1.y : (k == 2) ? wv1.z : wv1.w;
                    float w2 = (k == 0) ? wv2.x : (k == 1) ? wv2.y : (k == 2) ? wv2.z : wv2.w;
                    float w3 = (k == 0) ? wv3.x : (k == 1) ? wv3.y : (k == 2) ? wv3.z : wv3.w;
                    a.x = fmaf(w0, xv.x, a.x);
                    a.y = fmaf(w1, xv.y, a.y);
                    a.z = fmaf(w2, xv.z, a.z);
                    a.w = fmaf(w3, xv.w, a.w);
                }
            }
            su[tt][dq + 0] = silu_f(a.x);
            su[tt][dq + 1] = silu_f(a.y);
            su[tt][dq + 2] = silu_f(a.z);
            su[tt][dq + 3] = silu_f(a.w);
        }
#pragma unroll
        for (int p = 0; p < 3; p++) {
            int lin = tid + p * 256;
            int r = lin >> 4, dq = lin & 15;
            float4 v = *(const float4*)&xproj_w[((size_t)i * 48 + r) * 512 + dk + dq * 4];
            sw[r][dq * 4 + 0] = v.x; sw[r][dq * 4 + 1] = v.y;
            sw[r][dq * 4 + 2] = v.z; sw[r][dq * 4 + 3] = v.w;
        }
        __syncthreads();
#pragma unroll 8
        for (int dd = 0; dd < 64; dd++) {
            float u0 = su[tx * 4 + 0][dd];
            float u1 = su[tx * 4 + 1][dd];
            float u2 = su[tx * 4 + 2][dd];
            float u3 = su[tx * 4 + 3][dd];
#pragma unroll
            for (int j = 0; j < 3; j++) {
                float wv = sw[ty * 3 + j][dd];
                acc[0][j] = fmaf(u0, wv, acc[0][j]);
                acc[1][j] = fmaf(u1, wv, acc[1][j]);
                acc[2][j] = fmaf(u2, wv, acc[2][j]);
                acc[3][j] = fmaf(u3, wv, acc[3][j]);
            }
        }
        __syncthreads();
    }
#pragma unroll
    for (int ii = 0; ii < 4; ii++) {
        int t = t0 + tx * 4 + ii;
#pragma unroll
        for (int j = 0; j < 3; j++) {
            int r = ty * 3 + j;
            float v = acc[ii][j];
            if (r < 16) g_dtlow[((size_t)ib * LSEQ + t) * 16 + r] = v;
            else        g_bcs[((size_t)ib * LSEQ + t) * 32 + (r - 16)] = v;
        }
    }
}

// ---------------- scan body (shared by k4a / k4c) ----------------
struct ScanShared {
    float sdt[32][20];
    float sbc[32][36];
};

template<bool FAST, bool PASSC>
__device__ __forceinline__ void scan_chunk_body(
    ScanShared* sh, int ib, int b, int c, int d, int tid,
    int sft, int rev, int msk,
    float4 wv, float cbv, const float* dtw, float dtb,
    const float* Av, float Dsk, float* h, float* Sout)
{
    const float* xb = g_xz + (size_t)b * LSEQ * 1024 + d;
    const float* zb = xb + 512;
    float x3 = 0.f, x2 = 0.f, x1 = 0.f;
    int t0c = c * LC;
    if (t0c >= 3) {
        x3 = xb[(size_t)perm_idx(t0c - 3, rev, sft, msk) * 1024];
        x2 = xb[(size_t)perm_idx(t0c - 2, rev, sft, msk) * 1024];
        x1 = xb[(size_t)perm_idx(t0c - 1, rev, sft, msk) * 1024];
    }
    float S = 0.f;
    for (int sub = 0; sub < 4; sub++) {
        int tb = t0c + sub * 32;
        __syncthreads();
        if (tid < 128) {
            int tt = tid >> 2, r4 = (tid & 3) * 4;
            *(float4*)&sh->sdt[tt][r4] =
                *(const float4*)&g_dtlow[((size_t)ib * LSEQ + tb + tt) * 16 + r4];
        }
        if (PASSC) {
            int tt = tid >> 3, s4 = (tid & 7) * 4;
            *(float4*)&sh->sbc[tt][s4] =
                *(const float4*)&g_bcs[((size_t)ib * LSEQ + tb + tt) * 32 + s4];
        } else if (tid >= 128) {
            int q = tid - 128;
            int tt = q >> 2, r4 = (q & 3) * 4;
            *(float4*)&sh->sbc[tt][r4] =
                *(const float4*)&g_bcs[((size_t)ib * LSEQ + tb + tt) * 32 + r4];
        }
        __syncthreads();
#pragma unroll 2
        for (int tt = 0; tt < 32; tt++) {
            int t = tb + tt;
            int l = perm_idx(t, rev, sft, msk);
            float xv = xb[(size_t)l * 1024];
            float ua = fmaf(wv.x, x3, fmaf(wv.y, x2, fmaf(wv.z, x1, fmaf(wv.w, xv, cbv))));
            x3 = x2; x2 = x1; x1 = xv;
            float u = silu_f(ua);
            float a = dtb;
            {
                const float4* q4 = (const float4*)&sh->sdt[tt][0];
                float4 q0 = q4[0], q1 = q4[1], q2 = q4[2], q3 = q4[3];
                a = fmaf(dtw[0], q0.x, a); a = fmaf(dtw[1], q0.y, a);
                a = fmaf(dtw[2], q0.z, a); a = fmaf(dtw[3], q0.w, a);
                a = fmaf(dtw[4], q1.x, a); a = fmaf(dtw[5], q1.y, a);
                a = fmaf(dtw[6], q1.z, a); a = fmaf(dtw[7], q1.w, a);
                a = fmaf(dtw[8], q2.x, a); a = fmaf(dtw[9], q2.y, a);
                a = fmaf(dtw[10], q2.z, a); a = fmaf(dtw[11], q2.w, a);
                a = fmaf(dtw[12], q3.x, a); a = fmaf(dtw[13], q3.y, a);
                a = fmaf(dtw[14], q3.z, a); a = fmaf(dtw[15], q3.w, a);
            }
            float delta = fmaxf(a, 0.f) + __logf(1.f + __expf(-fabsf(a)));
            S += delta;
            float dub = delta * u;
            float4 b0 = *(const float4*)&sh->sbc[tt][0];
            float4 b1 = *(const float4*)&sh->sbc[tt][4];
            float4 b2 = *(const float4*)&sh->sbc[tt][8];
            float4 b3 = *(const float4*)&sh->sbc[tt][12];
            float dA[16];
            if (FAST) {
                float E = __expf(-delta);
                float p2 = E * E, p3 = p2 * E, p4 = p2 * p2;
                dA[0] = E;  dA[1] = p2;      dA[2] = p3;      dA[3] = p4;
                dA[4] = p4 * E;  dA[5] = p4 * p2;  dA[6] = p4 * p3;  dA[7] = p4 * p4;
                float p8 = dA[7];
                dA[8]  = p8 * E;      dA[9]  = p8 * p2;     dA[10] = p8 * p3;
                dA[11] = p8 * p4;     dA[12] = p8 * dA[4];  dA[13] = p8 * dA[5];
                dA[14] = p8 * dA[6];  dA[15] = p8 * p8;
            } else {
#pragma unroll
                for (int n = 0; n < 16; n++) dA[n] = __expf(delta * Av[n]);
            }
            float bn[16] = {b0.x, b0.y, b0.z, b0.w, b1.x, b1.y, b1.z, b1.w,
                            b2.x, b2.y, b2.z, b2.w, b3.x, b3.y, b3.z, b3.w};
#pragma unroll
            for (int n = 0; n < 16; n++) h[n] = fmaf(dA[n], h[n], dub * bn[n]);
            if (PASSC) {
                float4 c0 = *(const float4*)&sh->sbc[tt][16];
                float4 c1 = *(const float4*)&sh->sbc[tt][20];
                float4 c2 = *(const float4*)&sh->sbc[tt][24];
                float4 c3 = *(const float4*)&sh->sbc[tt][28];
                float cn[16] = {c0.x, c0.y, c0.z, c0.w, c1.x, c1.y, c1.z, c1.w,
                                c2.x, c2.y, c2.z, c2.w, c3.x, c3.y, c3.z, c3.w};
                float y = 0.f;
#pragma unroll
                for (int n = 0; n < 16; n++) y = fmaf(h[n], cn[n], y);
                float z = zb[(size_t)l * 1024];
                float outv = (y + u * Dsk) * silu_f(z);
                g_y[((size_t)ib * LSEQ + t) * 512 + d] = outv;
            }
        }
    }
    *Sout = S;
}

__global__ void __launch_bounds__(256) k4a_chunk(const float* __restrict__ A_log,
                                                 const float* __restrict__ conv_w,
                                                 const float* __restrict__ conv_b,
                                                 const float* __restrict__ dt_w,
                                                 const float* __restrict__ dt_b)
{
    __shared__ ScanShared sh;
    int bi = blockIdx.x;
    int half = bi & 1, c = (bi >> 1) & 15, ib = bi >> 5;
    int i = ib >> 1, b = ib & 1;
    int tid = threadIdx.x;
    int d = half * 256 + tid;
    int sft = (i < 2) ? 11 : ((i < 4) ? 6 : 4);
    int rev = i & 1;
    int msk = (1 << sft) - 1;
    float4 wv = *(const float4*)&conv_w[((size_t)i * 512 + d) * 4];
    float cbv = conv_b[i * 512 + d];
    float dtw[16];
#pragma unroll
    for (int r = 0; r < 16; r += 4) {
        float4 v = *(const float4*)&dt_w[((size_t)i * 512 + d) * 16 + r];
        dtw[r] = v.x; dtw[r + 1] = v.y; dtw[r + 2] = v.z; dtw[r + 3] = v.w;
    }
    float dtb = dt_b[i * 512 + d];
    float Av[16];
    bool fast = true;
#pragma unroll
    for (int n = 0; n < 16; n++) {
        Av[n] = -__expf(A_log[((size_t)i * 512 + d) * 16 + n]);
        fast = fast && (fabsf(Av[n] + (float)(n + 1)) < 1e-4f * (float)(n + 1));
    }
    float h[16];
#pragma unroll
    for (int n = 0; n < 16; n++) h[n] = 0.f;
    float S = 0.f;
    if (fast) scan_chunk_body<true, false>(&sh, ib, b, c, d, tid, sft, rev, msk,
                                           wv, cbv, dtw, dtb, Av, 0.f, h, &S);
    else      scan_chunk_body<false, false>(&sh, ib, b, c, d, tid, sft, rev, msk,
                                            wv, cbv, dtw, dtb, Av, 0.f, h, &S);
    size_t base = (((size_t)ib * 16 + c) * 512 + d) * 16;
    float P[16];
    if (fast) {
        float F = __expf(-S);
        float p2 = F * F, p3 = p2 * F, p4 = p2 * p2;
        P[0] = F; P[1] = p2; P[2] = p3; P[3] = p4;
        P[4] = p4 * F; P[5] = p4 * p2; P[6] = p4 * p3; P[7] = p4 * p4;
        float p8 = P[7];
        P[8] = p8 * F; P[9] = p8 * p2; P[10] = p8 * p3; P[11] = p8 * p4;
        P[12] = p8 * P[4]; P[13] = p8 * P[5]; P[14] = p8 * P[6]; P[15] = p8 * p8;
    } else {
#pragma unroll
        for (int n = 0; n < 16; n++) P[n] = __expf(Av[n] * S);
    }
#pragma unroll
    for (int n = 0; n < 16; n++) {
        g_P[base + n] = P[n];
        g_q[base + n] = h[n];
    }
}

__global__ void __launch_bounds__(256) k4b_carry()
{
    int gid = blockIdx.x * 256 + threadIdx.x;  // 98304 = 12*512*16
    float h = 0.f;
    size_t base0 = (size_t)gid % (512 * 16);
    int ib = gid / (512 * 16);
    size_t stride = (size_t)512 * 16;
    size_t b0 = (size_t)ib * 16 * stride + base0;
    for (int c = 0; c < 16; c++) {
        size_t idx = b0 + c * stride;
        g_hin[idx] = h;
        h = fmaf(g_P[idx], h, g_q[idx]);
    }
}

__global__ void __launch_bounds__(256) k4c_scan(const float* __restrict__ A_log,
                                                const float* __restrict__ conv_w,
                                                const float* __restrict__ conv_b,
                                                const float* __restrict__ dt_w,
                                                const float* __restrict__ dt_b,
                                                const float* __restrict__ D_skip)
{
    __shared__ ScanShared sh;
    int bi = blockIdx.x;
    int half = bi & 1, c = (bi >> 1) & 15, ib = bi >> 5;
    int i = ib >> 1, b = ib & 1;
    int tid = threadIdx.x;
    int d = half * 256 + tid;
    int sft = (i < 2) ? 11 : ((i < 4) ? 6 : 4);
    int rev = i & 1;
    int msk = (1 << sft) - 1;
    float4 wv = *(const float4*)&conv_w[((size_t)i * 512 + d) * 4];
    float cbv = conv_b[i * 512 + d];
    float dtw[16];
#pragma unroll
    for (int r = 0; r < 16; r += 4) {
        float4 v = *(const float4*)&dt_w[((size_t)i * 512 + d) * 16 + r];
        dtw[r] = v.x; dtw[r + 1] = v.y; dtw[r + 2] = v.z; dtw[r + 3] = v.w;
    }
    float dtb = dt_b[i * 512 + d];
    float Dsk = D_skip[i * 512 + d];
    float Av[16];
    bool fast = true;
#pragma unroll
    for (int n = 0; n < 16; n++) {
        Av[n] = -__expf(A_log[((size_t)i * 512 + d) * 16 + n]);
        fast = fast && (fabsf(Av[n] + (float)(n + 1)) < 1e-4f * (float)(n + 1));
    }
    float h[16];
    {
        size_t base = (((size_t)ib * 16 + c) * 512 + d) * 16;
#pragma unroll
        for (int n = 0; n < 16; n++) h[n] = g_hin[base + n];
    }
    float S;
    if (fast) scan_chunk_body<true, true>(&sh, ib, b, c, d, tid, sft, rev, msk,
                                          wv, cbv, dtw, dtb, Av, Dsk, h, &S);
    else      scan_chunk_body<false, true>(&sh, ib, b, c, d, tid, sft, rev, msk,
                                           wv, cbv, dtw, dtb, Av, Dsk, h, &S);
}

// ---------------- K5: total[b][l][d] = sum over branches ----------------
__global__ void __launch_bounds__(256) k5_sum()
{
    int gid = blockIdx.x * 256 + threadIdx.x;
    int d = gid & 511;
    int l = (gid >> 9) & 2047;
    int b = gid >> 20;
    int t64 = ((l & 31) << 6) | (l >> 5);
    int t16 = ((l & 127) << 4) | (l >> 7);
    size_t per_ib = (size_t)LSEQ * 512;
    float s;
    s  = g_y[(0 + b) * per_ib + (size_t)l * 512 + d];
    s += g_y[(2 + b) * per_ib + (size_t)(2047 - l) * 512 + d];
    s += g_y[(4 + b) * per_ib + (size_t)t64 * 512 + d];
    s += g_y[(6 + b) * per_ib + (size_t)t64 * 512 + d];
    s += g_y[(8 + b) * per_ib + (size_t)t16 * 512 + d];
    s += g_y[(10 + b) * per_ib + (size_t)t16 * 512 + d];
    g_total[((size_t)b * LSEQ + l) * 512 + d] = s;
}

// ---------------- K6: out[m][o] = sum_k total[m][k]*out_w[o][k] (M=4096,N=256,K=512) ----------------
__global__ void __launch_bounds__(256) k6_gemm_out(const float* __restrict__ out_w,
                                                   float* __restrict__ out)
{
    __shared__ __align__(16) float sa[16][132];
    __shared__ __align__(16) float sb[16][68];
    int m0 = blockIdx.x * 128, o0 = blockIdx.y * 64;
    int tid = threadIdx.x;
    int tx = tid & 15, ty = tid >> 4;
    ull acc[8][2];
#pragma unroll
    for (int ii = 0; ii < 8; ii++) { acc[ii][0] = 0ull; acc[ii][1] = 0ull; }
    int rowa = tid >> 1, kh = (tid & 1) * 8;
    int rowb = tid >> 2, kq = (tid & 3) * 4;
    for (int k0 = 0; k0 < 512; k0 += 16) {
#pragma unroll
        for (int q = 0; q < 2; q++) {
            float4 v = *(const float4*)&g_total[(size_t)(m0 + rowa) * 512 + k0 + kh + q * 4];
            sa[kh + q * 4 + 0][rowa] = v.x; sa[kh + q * 4 + 1][rowa] = v.y;
            sa[kh + q * 4 + 2][rowa] = v.z; sa[kh + q * 4 + 3][rowa] = v.w;
        }
        {
            float4 w = *(const float4*)&out_w[(size_t)(o0 + rowb) * 512 + k0 + kq];
            sb[kq + 0][rowb] = w.x; sb[kq + 1][rowb] = w.y;
            sb[kq + 2][rowb] = w.z; sb[kq + 3][rowb] = w.w;
        }
        __syncthreads();
#pragma unroll
        for (int kk = 0; kk < 16; kk++) {
            float4 a0 = *(float4*)&sa[kk][ty * 8];
            float4 a1 = *(float4*)&sa[kk][ty * 8 + 4];
            float4 bv = *(float4*)&sb[kk][tx * 4];
            ull bp[2] = {pack2(bv.x, bv.y), pack2(bv.z, bv.w)};
            float av[8] = {a0.x, a0.y, a0.z, a0.w, a1.x, a1.y, a1.z, a1.w};
#pragma unroll
            for (int ii = 0; ii < 8; ii++) {
                ull ap = pack2(av[ii], av[ii]);
                ffma2(acc[ii][0], ap, bp[0]);
                ffma2(acc[ii][1], ap, bp[1]);
            }
        }
        __syncthreads();
    }
#pragma unroll
    for (int ii = 0; ii < 8; ii++) {
        float2 c0 = unpack2(acc[ii][0]), c1 = unpack2(acc[ii][1]);
        float4 v = make_float4(c0.x, c0.y, c1.x, c1.y);
        *(float4*)&out[(size_t)(m0 + ty * 8 + ii) * 256 + o0 + tx * 4] = v;
    }
}

extern "C" void kernel_launch(void* const* d_in, const int* in_sizes, int n_in,
                              void* d_out, int out_size)
{
    const float* hs      = (const float*)d_in[0];
    const float* in_w    = (const float*)d_in[1];
    const float* out_w   = (const float*)d_in[2];
    const float* conv_w  = (const float*)d_in[3];
    const float* conv_b  = (const float*)d_in[4];
    const float* xproj_w = (const float*)d_in[5];
    const float* dt_w    = (const float*)d_in[6];
    const float* dt_b    = (const float*)d_in[7];
    const float* A_log   = (const float*)d_in[8];
    const float* D_skip  = (const float*)d_in[9];
    float* out = (float*)d_out;

    k1_gemm_in<<<dim3(32, 8), 256>>>(hs, in_w);
    k3a_xproj<<<dim3(32, 12), 256>>>(xproj_w, conv_w, conv_b);
    k4a_chunk<<<384, 256>>>(A_log, conv_w, conv_b, dt_w, dt_b);
    k4b_carry<<<384, 256>>>();
    k4c_scan<<<384, 256>>>(A_log, conv_w, conv_b, dt_w, dt_b, D_skip);
    k5_sum<<<8192, 256>>>();
    k6_gemm_out<<<dim3(32, 4), 256>>>(out_w, out);
}

// round 6
// speedup vs baseline: 5.2885x; 1.1649x over previous
#include <cuda_runtime.h>
#include <math.h>

// Mamba 6-branch fused pipeline, fp32, chunked parallel scan, f32x2-packed.
// B=2, L=2048, D_MODEL=256, D_INNER=512, N=16, DT_RANK=16, 12 (branch,batch) streams
#define LSEQ 2048
#define DI   512
#define NIB  12
#define LC   64
#define NCH  32

typedef unsigned long long ull;

// -------- scratch (device globals) --------
__device__ float g_xz[2 * LSEQ * 1024];        // [b][l][e]
__device__ float g_dtlow[NIB * LSEQ * 16];     // [ib][t][r]
__device__ float g_bcs[NIB * LSEQ * 32];       // [ib][t][s] s<16:B, s>=16:C
__device__ float g_P[NIB * NCH * DI * 16];
__device__ float g_q[NIB * NCH * DI * 16];
__device__ float g_hin[NIB * NCH * DI * 16];
__device__ float g_total[2 * LSEQ * DI];       // [b][l][d]

__device__ __forceinline__ float silu_f(float v) {
    float e = __expf(-fabsf(v));
    return ((v >= 0.f) ? v : v * e) / (1.f + e);
}
__device__ __forceinline__ int perm_idx(int tau, int rev, int sft, int msk) {
    int base = rev ? (2047 - tau) : tau;
    return ((base & msk) << (11 - sft)) | (base >> sft);
}
__device__ __forceinline__ ull pack2(float lo, float hi) {
    ull r; asm("mov.b64 %0, {%1,%2};" : "=l"(r) : "f"(lo), "f"(hi)); return r;
}
__device__ __forceinline__ void ffma2(ull& d, ull a, ull b) {       // d = a*b + d
    asm("fma.rn.f32x2 %0, %1, %2, %0;" : "+l"(d) : "l"(a), "l"(b));
}
__device__ __forceinline__ ull ffma2_3(ull a, ull b, ull c) {       // a*b + c
    ull r; asm("fma.rn.f32x2 %0, %1, %2, %3;" : "=l"(r) : "l"(a), "l"(b), "l"(c)); return r;
}
__device__ __forceinline__ ull fmul2(ull a, ull b) {
    ull r; asm("mul.rn.f32x2 %0, %1, %2;" : "=l"(r) : "l"(a), "l"(b)); return r;
}
__device__ __forceinline__ float2 unpack2(ull v) {
    float2 f; asm("mov.b64 {%0,%1}, %2;" : "=f"(f.x), "=f"(f.y) : "l"(v)); return f;
}

// ---------------- K0: zero g_total ----------------
__global__ void __launch_bounds__(256) k0_zero()
{
    int gid = blockIdx.x * 256 + threadIdx.x;
    *(float4*)&g_total[(size_t)gid * 4] = make_float4(0.f, 0.f, 0.f, 0.f);
}

// ---------------- K1: xz[m][e] = sum_k hs[m][k]*in_w[e][k] (M=4096,N=1024,K=256) ----------------
__global__ void __launch_bounds__(256) k1_gemm_in(const float* __restrict__ hs,
                                                  const float* __restrict__ in_w)
{
    __shared__ __align__(16) float sa[16][132];
    __shared__ __align__(16) float sb[16][132];
    int m0 = blockIdx.x * 128, n0 = blockIdx.y * 128;
    int tid = threadIdx.x;
    int tx = tid & 15, ty = tid >> 4;
    ull acc[8][4];
#pragma unroll
    for (int ii = 0; ii < 8; ii++)
#pragma unroll
        for (int jj = 0; jj < 4; jj++) acc[ii][jj] = 0ull;
    int rowa = tid >> 1, kh = (tid & 1) * 8;
    for (int k0 = 0; k0 < 256; k0 += 16) {
#pragma unroll
        for (int q = 0; q < 2; q++) {
            float4 v = *(const float4*)&hs[(size_t)(m0 + rowa) * 256 + k0 + kh + q * 4];
            sa[kh + q * 4 + 0][rowa] = v.x; sa[kh + q * 4 + 1][rowa] = v.y;
            sa[kh + q * 4 + 2][rowa] = v.z; sa[kh + q * 4 + 3][rowa] = v.w;
            float4 w = *(const float4*)&in_w[(size_t)(n0 + rowa) * 256 + k0 + kh + q * 4];
            sb[kh + q * 4 + 0][rowa] = w.x; sb[kh + q * 4 + 1][rowa] = w.y;
            sb[kh + q * 4 + 2][rowa] = w.z; sb[kh + q * 4 + 3][rowa] = w.w;
        }
        __syncthreads();
#pragma unroll
        for (int kk = 0; kk < 16; kk++) {
            float4 a0 = *(float4*)&sa[kk][ty * 8];
            float4 a1 = *(float4*)&sa[kk][ty * 8 + 4];
            float4 b0 = *(float4*)&sb[kk][tx * 8];
            float4 b1 = *(float4*)&sb[kk][tx * 8 + 4];
            ull bp[4] = {pack2(b0.x, b0.y), pack2(b0.z, b0.w),
                         pack2(b1.x, b1.y), pack2(b1.z, b1.w)};
            float av[8] = {a0.x, a0.y, a0.z, a0.w, a1.x, a1.y, a1.z, a1.w};
#pragma unroll
            for (int ii = 0; ii < 8; ii++) {
                ull ap = pack2(av[ii], av[ii]);
#pragma unroll
                for (int jj = 0; jj < 4; jj++) ffma2(acc[ii][jj], ap, bp[jj]);
            }
        }
        __syncthreads();
    }
#pragma unroll
    for (int ii = 0; ii < 8; ii++) {
        float2 c0 = unpack2(acc[ii][0]), c1 = unpack2(acc[ii][1]);
        float2 c2 = unpack2(acc[ii][2]), c3 = unpack2(acc[ii][3]);
        float4 v0 = make_float4(c0.x, c0.y, c1.x, c1.y);
        float4 v1 = make_float4(c2.x, c2.y, c3.x, c3.y);
        size_t base = (size_t)(m0 + ty * 8 + ii) * 1024 + n0 + tx * 8;
        *(float4*)&g_xz[base]     = v0;
        *(float4*)&g_xz[base + 4] = v1;
    }
}

// ---------------- K3a: fused conv+silu u, x_dbl[ib][t][r] = sum_d u[t][d]*xproj_w[i][r][d] ----------------
__global__ void __launch_bounds__(256) k3a_xproj(const float* __restrict__ xproj_w,
                                                 const float* __restrict__ conv_w,
                                                 const float* __restrict__ conv_b)
{
    __shared__ float su[64][65];
    __shared__ float sw[48][65];
    int ib = blockIdx.y, i = ib >> 1, b = ib & 1;
    int t0 = blockIdx.x * 64;
    int tid = threadIdx.x;
    int tx = tid & 15, ty = tid >> 4;
    int sft = (i < 2) ? 11 : ((i < 4) ? 6 : 4);
    int rev = i & 1;
    int msk = (1 << sft) - 1;
    const float* xb = g_xz + (size_t)b * LSEQ * 1024;
    ull acc2[2][3];
#pragma unroll
    for (int ii = 0; ii < 2; ii++)
#pragma unroll
        for (int j = 0; j < 3; j++) acc2[ii][j] = 0ull;

    for (int dk = 0; dk < 512; dk += 64) {
#pragma unroll
        for (int p = 0; p < 4; p++) {
            int lin = tid + p * 256;
            int tt = lin >> 4, dq = (lin & 15) * 4;
            int dcol = dk + dq;
            float4 wv0 = *(const float4*)&conv_w[((size_t)i * 512 + dcol + 0) * 4];
            float4 wv1 = *(const float4*)&conv_w[((size_t)i * 512 + dcol + 1) * 4];
            float4 wv2 = *(const float4*)&conv_w[((size_t)i * 512 + dcol + 2) * 4];
            float4 wv3 = *(const float4*)&conv_w[((size_t)i * 512 + dcol + 3) * 4];
            float4 a = *(const float4*)&conv_b[i * 512 + dcol];
#pragma unroll
            for (int k = 0; k < 4; k++) {
                int tau = t0 + tt - 3 + k;
                if (tau >= 0) {
                    int l = perm_idx(tau, rev, sft, msk);
                    float4 xv = *(const float4*)&xb[(size_t)l * 1024 + dcol];
                    float w0 = (k == 0) ? wv0.x : (k == 1) ? wv0.y : (k == 2) ? wv0.z : wv0.w;
                    float w1 = (k == 0) ? wv1.x : (k == 1) ? wv1.y : (k == 2) ? wv1.z : wv1.w;
                    float w2 = (k == 0) ? wv2.x : (k == 1) ? wv2.y : (k == 2) ? wv2.z : wv2.w;
                    float w3 = (k == 0) ? wv3.x : (k == 1) ? wv3.y : (k == 2) ? wv3.z : wv3.w;
                    a.x = fmaf(w0, xv.x, a.x);
                    a.y = fmaf(w1, xv.y, a.y);
                    a.z = fmaf(w2, xv.z, a.z);
                    a.w = fmaf(w3, xv.w, a.w);
                }
            }
            su[tt][dq + 0] = silu_f(a.x);
            su[tt][dq + 1] = silu_f(a.y);
            su[tt][dq + 2] = silu_f(a.z);
            su[tt][dq + 3] = silu_f(a.w);
        }
#pragma unroll
        for (int p = 0; p < 3; p++) {
            int lin = tid + p * 256;
            int r = lin >> 4, dq = lin & 15;
            float4 v = *(const float4*)&xproj_w[((size_t)i * 48 + r) * 512 + dk + dq * 4];
            sw[r][dq * 4 + 0] = v.x; sw[r][dq * 4 + 1] = v.y;
            sw[r][dq * 4 + 2] = v.z; sw[r][dq * 4 + 3] = v.w;
        }
        __syncthreads();
#pragma unroll 8
        for (int dd = 0; dd < 64; dd++) {
            ull up0 = pack2(su[tx * 4 + 0][dd], su[tx * 4 + 1][dd]);
            ull up1 = pack2(su[tx * 4 + 2][dd], su[tx * 4 + 3][dd]);
#pragma unroll
            for (int j = 0; j < 3; j++) {
                float wvv = sw[ty * 3 + j][dd];
                ull wvp = pack2(wvv, wvv);
                ffma2(acc2[0][j], up0, wvp);
                ffma2(acc2[1][j], up1, wvp);
            }
        }
        __syncthreads();
    }
#pragma unroll
    for (int j = 0; j < 3; j++) {
        float2 lo = unpack2(acc2[0][j]);
        float2 hi = unpack2(acc2[1][j]);
        float vals[4] = {lo.x, lo.y, hi.x, hi.y};
        int r = ty * 3 + j;
#pragma unroll
        for (int ii = 0; ii < 4; ii++) {
            int t = t0 + tx * 4 + ii;
            float v = vals[ii];
            if (r < 16) g_dtlow[((size_t)ib * LSEQ + t) * 16 + r] = v;
            else        g_bcs[((size_t)ib * LSEQ + t) * 32 + (r - 16)] = v;
        }
    }
}

// ---------------- scan shared staging ----------------
// NOTE: row strides MUST keep float4 (16B) alignment: 20 floats = 80B, 36 floats = 144B.
struct __align__(16) ScanShared {
    float sdt[32][20];
    float sbc[32][36];
};

__device__ __forceinline__ void stage_tile(ScanShared* sh, int ib, int tb, int tid, bool passc)
{
    __syncthreads();
    if (tid < 128) {
        int tt = tid >> 2, r4 = (tid & 3) * 4;
        *(float4*)&sh->sdt[tt][r4] =
            *(const float4*)&g_dtlow[((size_t)ib * LSEQ + tb + tt) * 16 + r4];
    }
    if (passc) {
        int tt = tid >> 3, s4 = (tid & 7) * 4;
        *(float4*)&sh->sbc[tt][s4] =
            *(const float4*)&g_bcs[((size_t)ib * LSEQ + tb + tt) * 32 + s4];
    } else if (tid >= 128) {
        int q = tid - 128;
        int tt = q >> 2, r4 = (q & 3) * 4;
        *(float4*)&sh->sbc[tt][r4] =
            *(const float4*)&g_bcs[((size_t)ib * LSEQ + tb + tt) * 32 + r4];
    }
    __syncthreads();
}

// ---------------- fast (A[n] = -(n+1)) packed scan body ----------------
template<bool PASSC>
__device__ __forceinline__ void scan_fast(
    ScanShared* sh, int ib, int b, int c, int d, int tid,
    int sft, int rev, int msk,
    float4 wv, float cbv, const ull* dtw2, float dtb,
    float Dsk, ull* h2, float* Sout)
{
    const float* xb = g_xz + (size_t)b * LSEQ * 1024 + d;
    const float* zb = xb + 512;
    float x3 = 0.f, x2 = 0.f, x1 = 0.f;
    int t0c = c * LC;
    if (t0c >= 3) {
        x3 = xb[(size_t)perm_idx(t0c - 3, rev, sft, msk) * 1024];
        x2 = xb[(size_t)perm_idx(t0c - 2, rev, sft, msk) * 1024];
        x1 = xb[(size_t)perm_idx(t0c - 1, rev, sft, msk) * 1024];
    }
    float S = 0.f;
    float* totb = g_total + (size_t)b * LSEQ * 512 + d;
    int i = ib >> 1;
    for (int sub = 0; sub < LC / 32; sub++) {
        int tb = t0c + sub * 32;
        stage_tile(sh, ib, tb, tid, PASSC);
#pragma unroll 2
        for (int tt = 0; tt < 32; tt++) {
            int t = tb + tt;
            int l = perm_idx(t, rev, sft, msk);
            float xv = xb[(size_t)l * 1024];
            float ua = fmaf(wv.x, x3, fmaf(wv.y, x2, fmaf(wv.z, x1, fmaf(wv.w, xv, cbv))));
            x3 = x2; x2 = x1; x1 = xv;
            float u = silu_f(ua);
            // delta = softplus(dtw . sdt + dtb), packed dot
            const ull* qd = (const ull*)&sh->sdt[tt][0];
            ull a2 = 0ull;
#pragma unroll
            for (int j = 0; j < 8; j++) ffma2(a2, dtw2[j], qd[j]);
            float2 as_ = unpack2(a2);
            float a = dtb + as_.x + as_.y;
            float delta = fmaxf(a, 0.f) + __logf(1.f + __expf(-fabsf(a)));
            S += delta;
            // dA[n] = E^(n+1), packed pairs
            float E = __expf(-delta);
            float E2 = E * E, E4 = E2 * E2, E8 = E4 * E4;
            ull d0 = pack2(E, E2);
            ull q4p = pack2(E4, E4), q8p = pack2(E8, E8);
            ull dA0 = d0;
            ull dA1 = fmul2(d0, pack2(E2, E2));
            ull dA2v = fmul2(d0, q4p);
            ull dA3 = fmul2(dA1, q4p);
            ull dA4 = fmul2(d0, q8p);
            ull dA5 = fmul2(dA1, q8p);
            ull dA6 = fmul2(dA2v, q8p);
            ull dA7 = fmul2(dA3, q8p);
            ull dApows[8] = {dA0, dA1, dA2v, dA3, dA4, dA5, dA6, dA7};
            float dub = delta * u;
            ull dubp = pack2(dub, dub);
            const ull* bp = (const ull*)&sh->sbc[tt][0];
#pragma unroll
            for (int j = 0; j < 8; j++)
                h2[j] = ffma2_3(dApows[j], h2[j], fmul2(dubp, bp[j]));
            if (PASSC) {
                const ull* cp = (const ull*)&sh->sbc[tt][16];
                ull y2 = 0ull;
#pragma unroll
                for (int j = 0; j < 8; j++) ffma2(y2, h2[j], cp[j]);
                float2 yy = unpack2(y2);
                float y = yy.x + yy.y;
                float z = zb[(size_t)l * 1024];
                float outv = (y + u * Dsk) * silu_f(z);
                int lout;
                if (i == 0)      lout = t;
                else if (i == 1) lout = 2047 - t;
                else if (i < 4)  lout = ((t & 63) << 5) | (t >> 6);
                else             lout = ((t & 15) << 7) | (t >> 4);
                atomicAdd(&totb[(size_t)lout * 512], outv);
            }
        }
    }
    *Sout = S;
}

// ---------------- slow fallback (general A), scalar ----------------
template<bool PASSC>
__device__ __noinline__ void scan_slow(
    ScanShared* sh, int ib, int b, int c, int d, int tid,
    int sft, int rev, int msk,
    float4 wv, float cbv, const ull* dtw2, float dtb,
    const float* A_log, float Dsk, float* h, float* Sout)
{
    int i = ib >> 1;
    float Av[16];
#pragma unroll
    for (int n = 0; n < 16; n++) Av[n] = -__expf(A_log[((size_t)i * 512 + d) * 16 + n]);
    const float* xb = g_xz + (size_t)b * LSEQ * 1024 + d;
    const float* zb = xb + 512;
    float x3 = 0.f, x2 = 0.f, x1 = 0.f;
    int t0c = c * LC;
    if (t0c >= 3) {
        x3 = xb[(size_t)perm_idx(t0c - 3, rev, sft, msk) * 1024];
        x2 = xb[(size_t)perm_idx(t0c - 2, rev, sft, msk) * 1024];
        x1 = xb[(size_t)perm_idx(t0c - 1, rev, sft, msk) * 1024];
    }
    float S = 0.f;
    float* totb = g_total + (size_t)b * LSEQ * 512 + d;
    for (int sub = 0; sub < LC / 32; sub++) {
        int tb = t0c + sub * 32;
        stage_tile(sh, ib, tb, tid, PASSC);
        for (int tt = 0; tt < 32; tt++) {
            int t = tb + tt;
            int l = perm_idx(t, rev, sft, msk);
            float xv = xb[(size_t)l * 1024];
            float ua = fmaf(wv.x, x3, fmaf(wv.y, x2, fmaf(wv.z, x1, fmaf(wv.w, xv, cbv))));
            x3 = x2; x2 = x1; x1 = xv;
            float u = silu_f(ua);
            const ull* qd = (const ull*)&sh->sdt[tt][0];
            ull a2 = 0ull;
#pragma unroll
            for (int j = 0; j < 8; j++) ffma2(a2, dtw2[j], qd[j]);
            float2 as_ = unpack2(a2);
            float a = dtb + as_.x + as_.y;
            float delta = fmaxf(a, 0.f) + __logf(1.f + __expf(-fabsf(a)));
            S += delta;
            float dub = delta * u;
            float y = 0.f;
#pragma unroll
            for (int n = 0; n < 16; n++) {
                float bn = sh->sbc[tt][n];
                h[n] = fmaf(__expf(delta * Av[n]), h[n], dub * bn);
                if (PASSC) y = fmaf(h[n], sh->sbc[tt][16 + n], y);
            }
            if (PASSC) {
                float z = zb[(size_t)l * 1024];
                float outv = (y + u * Dsk) * silu_f(z);
                int lout;
                if (i == 0)      lout = t;
                else if (i == 1) lout = 2047 - t;
                else if (i < 4)  lout = ((t & 63) << 5) | (t >> 6);
                else             lout = ((t & 15) << 7) | (t >> 4);
                atomicAdd(&totb[(size_t)lout * 512], outv);
            }
        }
    }
    *Sout = S;
}

__device__ __forceinline__ bool check_fast(const float* A_log, int i, int d) {
    bool fast = true;
#pragma unroll
    for (int n = 0; n < 16; n++) {
        float Av = __expf(A_log[((size_t)i * 512 + d) * 16 + n]);
        fast = fast && (fabsf(Av - (float)(n + 1)) < 1e-4f * (float)(n + 1));
    }
    return fast;
}

__global__ void __launch_bounds__(256) k4a_chunk(const float* __restrict__ A_log,
                                                 const float* __restrict__ conv_w,
                                                 const float* __restrict__ conv_b,
                                                 const float* __restrict__ dt_w,
                                                 const float* __restrict__ dt_b)
{
    __shared__ ScanShared sh;
    int bi = blockIdx.x;                  // 768 = 12 ib * 32 c * 2 half
    int half = bi & 1, c = (bi >> 1) & 31, ib = bi >> 6;
    int i = ib >> 1, b = ib & 1;
    int tid = threadIdx.x;
    int d = half * 256 + tid;
    int sft = (i < 2) ? 11 : ((i < 4) ? 6 : 4);
    int rev = i & 1;
    int msk = (1 << sft) - 1;
    float4 wv = *(const float4*)&conv_w[((size_t)i * 512 + d) * 4];
    float cbv = conv_b[i * 512 + d];
    ull dtw2[8];
#pragma unroll
    for (int r = 0; r < 16; r += 4) {
        float4 v = *(const float4*)&dt_w[((size_t)i * 512 + d) * 16 + r];
        dtw2[r / 2]     = pack2(v.x, v.y);
        dtw2[r / 2 + 1] = pack2(v.z, v.w);
    }
    float dtb = dt_b[i * 512 + d];
    bool fast = check_fast(A_log, i, d);
    float S = 0.f;
    size_t base = (((size_t)ib * NCH + c) * 512 + d) * 16;
    if (fast) {
        ull h2[8];
#pragma unroll
        for (int j = 0; j < 8; j++) h2[j] = 0ull;
        scan_fast<false>(&sh, ib, b, c, d, tid, sft, rev, msk, wv, cbv, dtw2, dtb, 0.f, h2, &S);
        ull* qb = (ull*)&g_q[base];
#pragma unroll
        for (int j = 0; j < 8; j++) qb[j] = h2[j];
        float F = __expf(-S);
        float F2 = F * F, F4 = F2 * F2, F8 = F4 * F4;
        ull f0 = pack2(F, F2);
        ull r4 = pack2(F4, F4), r8 = pack2(F8, F8);
        ull P0 = f0;
        ull P1 = fmul2(f0, pack2(F2, F2));
        ull P2 = fmul2(f0, r4);
        ull P3 = fmul2(P1, r4);
        ull* pb = (ull*)&g_P[base];
        pb[0] = P0; pb[1] = P1; pb[2] = P2; pb[3] = P3;
        pb[4] = fmul2(P0, r8); pb[5] = fmul2(P1, r8);
        pb[6] = fmul2(P2, r8); pb[7] = fmul2(P3, r8);
    } else {
        float h[16];
#pragma unroll
        for (int n = 0; n < 16; n++) h[n] = 0.f;
        scan_slow<false>(&sh, ib, b, c, d, tid, sft, rev, msk, wv, cbv, dtw2, dtb, A_log, 0.f, h, &S);
#pragma unroll
        for (int n = 0; n < 16; n++) {
            float Av = -__expf(A_log[((size_t)i * 512 + d) * 16 + n]);
            g_P[base + n] = __expf(Av * S);
            g_q[base + n] = h[n];
        }
    }
}

// ---------------- K4b: inter-chunk scan (32 steps, prefetched) ----------------
__global__ void __launch_bounds__(256) k4b_carry()
{
    int gid = blockIdx.x * 256 + threadIdx.x;   // 98304 = 12*512*16
    size_t base0 = (size_t)gid % (512 * 16);
    int ib = gid / (512 * 16);
    size_t stride = (size_t)512 * 16;
    size_t b0 = (size_t)ib * NCH * stride + base0;
    float h = 0.f;
#pragma unroll
    for (int batch = 0; batch < 2; batch++) {
        float P[16], q[16];
#pragma unroll
        for (int j = 0; j < 16; j++) {
            size_t idx = b0 + (size_t)(batch * 16 + j) * stride;
            P[j] = g_P[idx];
            q[j] = g_q[idx];
        }
#pragma unroll
        for (int j = 0; j < 16; j++) {
            size_t idx = b0 + (size_t)(batch * 16 + j) * stride;
            g_hin[idx] = h;
            h = fmaf(P[j], h, q[j]);
        }
    }
}

__global__ void __launch_bounds__(256) k4c_scan(const float* __restrict__ A_log,
                                                const float* __restrict__ conv_w,
                                                const float* __restrict__ conv_b,
                                                const float* __restrict__ dt_w,
                                                const float* __restrict__ dt_b,
                                                const float* __restrict__ D_skip)
{
    __shared__ ScanShared sh;
    int bi = blockIdx.x;
    int half = bi & 1, c = (bi >> 1) & 31, ib = bi >> 6;
    int i = ib >> 1, b = ib & 1;
    int tid = threadIdx.x;
    int d = half * 256 + tid;
    int sft = (i < 2) ? 11 : ((i < 4) ? 6 : 4);
    int rev = i & 1;
    int msk = (1 << sft) - 1;
    float4 wv = *(const float4*)&conv_w[((size_t)i * 512 + d) * 4];
    float cbv = conv_b[i * 512 + d];
    ull dtw2[8];
#pragma unroll
    for (int r = 0; r < 16; r += 4) {
        float4 v = *(const float4*)&dt_w[((size_t)i * 512 + d) * 16 + r];
        dtw2[r / 2]     = pack2(v.x, v.y);
        dtw2[r / 2 + 1] = pack2(v.z, v.w);
    }
    float dtb = dt_b[i * 512 + d];
    float Dsk = D_skip[i * 512 + d];
    bool fast = check_fast(A_log, i, d);
    float S;
    size_t base = (((size_t)ib * NCH + c) * 512 + d) * 16;
    if (fast) {
        ull h2[8];
        const ull* hb = (const ull*)&g_hin[base];
#pragma unroll
        for (int j = 0; j < 8; j++) h2[j] = hb[j];
        scan_fast<true>(&sh, ib, b, c, d, tid, sft, rev, msk, wv, cbv, dtw2, dtb, Dsk, h2, &S);
    } else {
        float h[16];
#pragma unroll
        for (int n = 0; n < 16; n++) h[n] = g_hin[base + n];
        scan_slow<true>(&sh, ib, b, c, d, tid, sft, rev, msk, wv, cbv, dtw2, dtb, A_log, Dsk, h, &S);
    }
}

// ---------------- K6: out[m][o] = sum_k total[m][k]*out_w[o][k] (M=4096,N=256,K=512) ----------------
__global__ void __launch_bounds__(256) k6_gemm_out(const float* __restrict__ out_w,
                                                   float* __restrict__ out)
{
    __shared__ __align__(16) float sa[16][132];
    __shared__ __align__(16) float sb[16][68];
    int m0 = blockIdx.x * 128, o0 = blockIdx.y * 64;
    int tid = threadIdx.x;
    int tx = tid & 15, ty = tid >> 4;
    ull acc[8][2];
#pragma unroll
    for (int ii = 0; ii < 8; ii++) { acc[ii][0] = 0ull; acc[ii][1] = 0ull; }
    int rowa = tid >> 1, kh = (tid & 1) * 8;
    int rowb = tid >> 2, kq = (tid & 3) * 4;
    for (int k0 = 0; k0 < 512; k0 += 16) {
#pragma unroll
        for (int q = 0; q < 2; q++) {
            float4 v = *(const float4*)&g_total[(size_t)(m0 + rowa) * 512 + k0 + kh + q * 4];
            sa[kh + q * 4 + 0][rowa] = v.x; sa[kh + q * 4 + 1][rowa] = v.y;
            sa[kh + q * 4 + 2][rowa] = v.z; sa[kh + q * 4 + 3][rowa] = v.w;
        }
        {
            float4 w = *(const float4*)&out_w[(size_t)(o0 + rowb) * 512 + k0 + kq];
            sb[kq + 0][rowb] = w.x; sb[kq + 1][rowb] = w.y;
            sb[kq + 2][rowb] = w.z; sb[kq + 3][rowb] = w.w;
        }
        __syncthreads();
#pragma unroll
        for (int kk = 0; kk < 16; kk++) {
            float4 a0 = *(float4*)&sa[kk][ty * 8];
            float4 a1 = *(float4*)&sa[kk][ty * 8 + 4];
            float4 bv = *(float4*)&sb[kk][tx * 4];
            ull bp[2] = {pack2(bv.x, bv.y), pack2(bv.z, bv.w)};
            float av[8] = {a0.x, a0.y, a0.z, a0.w, a1.x, a1.y, a1.z, a1.w};
#pragma unroll
            for (int ii = 0; ii < 8; ii++) {
                ull ap = pack2(av[ii], av[ii]);
                ffma2(acc[ii][0], ap, bp[0]);
                ffma2(acc[ii][1], ap, bp[1]);
            }
        }
        __syncthreads();
    }
#pragma unroll
    for (int ii = 0; ii < 8; ii++) {
        float2 c0 = unpack2(acc[ii][0]), c1 = unpack2(acc[ii][1]);
        float4 v = make_float4(c0.x, c0.y, c1.x, c1.y);
        *(float4*)&out[(size_t)(m0 + ty * 8 + ii) * 256 + o0 + tx * 4] = v;
    }
}

extern "C" void kernel_launch(void* const* d_in, const int* in_sizes, int n_in,
                              void* d_out, int out_size)
{
    const float* hs      = (const float*)d_in[0];
    const float* in_w    = (const float*)d_in[1];
    const float* out_w   = (const float*)d_in[2];
    const float* conv_w  = (const float*)d_in[3];
    const float* conv_b  = (const float*)d_in[4];
    const float* xproj_w = (const float*)d_in[5];
    const float* dt_w    = (const float*)d_in[6];
    const float* dt_b    = (const float*)d_in[7];
    const float* A_log   = (const float*)d_in[8];
    const float* D_skip  = (const float*)d_in[9];
    float* out = (float*)d_out;

    k0_zero<<<2048, 256>>>();
    k1_gemm_in<<<dim3(32, 8), 256>>>(hs, in_w);
    k3a_xproj<<<dim3(32, 12), 256>>>(xproj_w, conv_w, conv_b);
    k4a_chunk<<<768, 256>>>(A_log, conv_w, conv_b, dt_w, dt_b);
    k4b_carry<<<384, 256>>>();
    k4c_scan<<<768, 256>>>(A_log, conv_w, conv_b, dt_w, dt_b, D_skip);
    k6_gemm_out<<<dim3(32, 4), 256>>>(out_w, out);
}